// round 13
// baseline (speedup 1.0000x reference)
#include <cuda_runtime.h>
#include <cuda_fp16.h>
#include <cstdint>
#include <math.h>

// LayerNorm(768) -> Linear(768->64) -> SiLU -> unpatchify, fused.
// LN folded into epilogue: y = rstd*(x@W'^T - mu*S) + b', W' = W*ln_w (fp16).
// fp16 mma.sync.m16n8k16. Warp-autonomous: each warp owns 16 rows x all 64
// cols, streams x through a private 4-stage cp.async smem ring (depth 3).
// 3 CTAs/SM; W' 32k-interleaved so each slab needs 8 LDG.128 per warp.

#define KDIM 768
#define ODIM 64
#define TILE_M 128
#define NTILES 1024            // 131072 / 128
#define NSLABS 24              // k-slabs of 32 floats (128B)

#define STAGE_F 512            // floats per warp-stage (16 rows x 32)
#define WARP_F  (4 * STAGE_F)  // 4-stage ring per warp
#define SMEM_DYN_BYTES (8 * WARP_F * 4)   // 64 KB per CTA

__device__ __half d_Wh[24 * ODIM * 32];   // [slab][o][32k frag-interleaved]
__device__ float d_S[ODIM];
__device__ float d_bp[ODIM];
__device__ unsigned d_ctr;

static __device__ __forceinline__ uint32_t s2u(const void* p) {
    uint32_t a;
    asm("{ .reg .u64 t; cvta.to.shared.u64 t, %1; cvt.u32.u64 %0, t; }" : "=r"(a) : "l"(p));
    return a;
}
static __device__ __forceinline__ uint32_t pack2(float lo, float hi) {
    uint32_t r;
    asm("cvt.rn.f16x2.f32 %0, %1, %2;" : "=r"(r) : "f"(hi), "f"(lo));
    return r;
}
static __device__ __forceinline__ void mma_f16(float* d,
    uint32_t a0, uint32_t a1, uint32_t a2, uint32_t a3,
    uint32_t b0, uint32_t b1)
{
    asm volatile(
        "mma.sync.aligned.m16n8k16.row.col.f32.f16.f16.f32 "
        "{%0,%1,%2,%3}, {%4,%5,%6,%7}, {%8,%9}, {%0,%1,%2,%3};"
        : "+f"(d[0]), "+f"(d[1]), "+f"(d[2]), "+f"(d[3])
        : "r"(a0), "r"(a1), "r"(a2), "r"(a3), "r"(b0), "r"(b1));
}
static __device__ __forceinline__ void cp16(uint32_t dst, const void* src) {
    asm volatile("cp.async.cg.shared.global [%0], [%1], 16;"
                 :: "r"(dst), "l"(src) : "memory");
}

// ---------------- merged prep kernel ----------------
// 32k interleave: k = s*32 + kl32; kc = kl32>>4, kl = kl32&15
// pos32 = ((kl&7)>>1)*8 + kc*4 + ((kl>>3)&1)*2 + (kl&1)
// -> lane q reads uint4 #q: {kc0 b0, kc0 b1, kc1 b0, kc1 b1}
__global__ void prep(const float* __restrict__ W, const float* __restrict__ lnw,
                     const float* __restrict__ lnb, const float* __restrict__ b,
                     unsigned ctr_init)
{
    __shared__ float red[2][8];
    const int bid = blockIdx.x, t = threadIdx.x;
    const int idx = bid * 256 + t;
    if (idx == 0) d_ctr = ctr_init;

    if (idx < ODIM * KDIM) {
        int o = idx / KDIM, k = idx - o * KDIM;
        int kl32 = k & 31;
        int kc = kl32 >> 4, kl = kl32 & 15;
        int pos = ((kl & 7) >> 1) * 8 + kc * 4 + ((kl >> 3) & 1) * 2 + (kl & 1);
        d_Wh[((k >> 5) * ODIM + o) * 32 + pos] = __float2half_rn(W[idx] * lnw[k]);
    }

    if (bid < ODIM) {
        const int o = bid;
        float s = 0.f, bs = 0.f;
        for (int k = t; k < KDIM; k += 256) {
            float w = W[o * KDIM + k];
            s  += __half2float(__float2half_rn(w * lnw[k]));
            bs += lnb[k] * w;
        }
        #pragma unroll
        for (int d = 16; d; d >>= 1) {
            s  += __shfl_xor_sync(0xffffffffu, s, d);
            bs += __shfl_xor_sync(0xffffffffu, bs, d);
        }
        if ((t & 31) == 0) { red[0][t >> 5] = s; red[1][t >> 5] = bs; }
        __syncthreads();
        if (t == 0) {
            float S = 0.f, B = 0.f;
            #pragma unroll
            for (int i = 0; i < 8; i++) { S += red[0][i]; B += red[1][i]; }
            d_S[o] = S;
            d_bp[o] = b[o] + B;
        }
    }
}

// ---------------- main kernel ----------------
extern __shared__ float sx[];

__global__ void __launch_bounds__(256, 3)
ln_gemm_silu(const float* __restrict__ x, float* __restrict__ out)
{
    __shared__ float sS[64], sbp[64];
    __shared__ unsigned s_next;

    const int tid  = threadIdx.x;
    const int lane = tid & 31;
    const int warp = tid >> 5;

    // consumer mapping: warp owns rows warp*16 + {u, u+8}, all 64 cols
    const int u = lane >> 2;
    const int q = lane & 3;

    // producer mapping: lane -> row pr = lane>>1, half ph = lane&1 (4x16B chunks)
    const int pr = lane >> 1;
    const int ph = lane & 1;

    if (tid < ODIM) { sS[tid] = d_S[tid]; sbp[tid] = d_bp[tid]; }
    __syncthreads();

    const uint32_t swb = s2u(sx) + warp * (WARP_F * 4);   // warp smem base (bytes)

    // producer byte offsets within a stage: row pr, chunks c=ph*4+j, swizzled
    uint32_t psw[4];
    #pragma unroll
    for (int j = 0; j < 4; j++) {
        int c = ph * 4 + j;
        psw[j] = (uint32_t)(pr * 128 + (((c ^ ((pr & 3) << 1)) << 2) << 2));
    }

    // consumer float offsets within a stage (rows u, u+8 share (r&3) swizzle)
    const int swl = (u & 3) << 1;
    const int pos = (q & 1) << 1;
    int coff[2][2];   // [kc][c-half] word offsets (row u; add 256 for u+8)
    #pragma unroll
    for (int kc = 0; kc < 2; kc++) {
        int c0 = kc * 4 + (q >> 1);
        coff[kc][0] = (((c0       ^ swl) << 2) + pos);
        coff[kc][1] = ((((c0 + 2) ^ swl) << 2) + pos);
    }
    const int rowu  = u * 32;
    const int rowu8 = (u + 8) * 32;

    const uint4* __restrict__ Wv = (const uint4*)d_Wh;

    unsigned tile = blockIdx.x;
    while (tile < NTILES) {
        float acc[8][4];
        #pragma unroll
        for (int nt = 0; nt < 8; nt++)
            #pragma unroll
            for (int c = 0; c < 4; c++) acc[nt][c] = 0.f;

        float st0 = 0.f, st1 = 0.f, st2 = 0.f, st3 = 0.f;

        const char* gx = (const char*)(x + (size_t)(tile * TILE_M + warp * 16 + pr) * KDIM)
                       + ph * 64;

        // ---- prologue: issue slabs 0..2 ----
        #pragma unroll
        for (int s = 0; s < 3; s++) {
            uint32_t d = swb + s * 2048;
            const char* g = gx + s * 128;
            #pragma unroll
            for (int j = 0; j < 4; j++) cp16(d + psw[j], g + j * 16);
            asm volatile("cp.async.commit_group;" ::: "memory");
        }

        #pragma unroll 2
        for (int s = 0; s < NSLABS; s++) {
            // issue slab s+3 (stage reuse safe: prev iter's mma.sync consumed it)
            if (s + 3 < NSLABS) {
                uint32_t d = swb + ((s + 3) & 3) * 2048;
                const char* g = gx + (s + 3) * 128;
                #pragma unroll
                for (int j = 0; j < 4; j++) cp16(d + psw[j], g + j * 16);
            }
            asm volatile("cp.async.commit_group;" ::: "memory");
            asm volatile("cp.async.wait_group 3;" ::: "memory");

            const float* sb = sx + warp * WARP_F + (s & 3) * STAGE_F;

            // load fragments from smem, stats, pack
            uint32_t af[2][4];
            #pragma unroll
            for (int kc = 0; kc < 2; kc++) {
                float2 vul = *(const float2*)&sb[rowu  + coff[kc][0]];
                float2 vuh = *(const float2*)&sb[rowu  + coff[kc][1]];
                float2 v8l = *(const float2*)&sb[rowu8 + coff[kc][0]];
                float2 v8h = *(const float2*)&sb[rowu8 + coff[kc][1]];
                st0 += vul.x + vul.y + vuh.x + vuh.y;
                st1 += vul.x*vul.x + vul.y*vul.y + vuh.x*vuh.x + vuh.y*vuh.y;
                st2 += v8l.x + v8l.y + v8h.x + v8h.y;
                st3 += v8l.x*v8l.x + v8l.y*v8l.y + v8h.x*v8h.x + v8h.y*v8h.y;
                af[kc][0] = pack2(vul.x, vul.y);   // (u,   2q)
                af[kc][1] = pack2(v8l.x, v8l.y);   // (u+8, 2q)
                af[kc][2] = pack2(vuh.x, vuh.y);   // (u,   2q+8)
                af[kc][3] = pack2(v8h.x, v8h.y);   // (u+8, 2q+8)
            }

            // W fragments: one LDG.128 per nt (both kc), then 2 MMAs
            const uint4* wb = Wv + (size_t)(s * ODIM + u) * 4 + q;
            #pragma unroll
            for (int nt = 0; nt < 8; nt++) {
                uint4 bv = __ldg(wb + nt * 32);   // +8 o-rows per nt
                mma_f16(acc[nt], af[0][0], af[0][1], af[0][2], af[0][3], bv.x, bv.y);
                mma_f16(acc[nt], af[1][0], af[1][1], af[1][2], af[1][3], bv.z, bv.w);
            }
        }

        // ---- row stats: reduce over 4 q-lanes sharing each row ----
        st0 += __shfl_xor_sync(0xffffffffu, st0, 1);
        st1 += __shfl_xor_sync(0xffffffffu, st1, 1);
        st2 += __shfl_xor_sync(0xffffffffu, st2, 1);
        st3 += __shfl_xor_sync(0xffffffffu, st3, 1);
        st0 += __shfl_xor_sync(0xffffffffu, st0, 2);
        st1 += __shfl_xor_sync(0xffffffffu, st1, 2);
        st2 += __shfl_xor_sync(0xffffffffu, st2, 2);
        st3 += __shfl_xor_sync(0xffffffffu, st3, 2);

        float mu[2], rs[2];
        mu[0] = st0 * (1.f / 768.f);
        mu[1] = st2 * (1.f / 768.f);
        rs[0] = rsqrtf(st1 * (1.f / 768.f) - mu[0] * mu[0] + 1e-5f);
        rs[1] = rsqrtf(st3 * (1.f / 768.f) - mu[1] * mu[1] + 1e-5f);

        // ---- epilogue: LN-correct, bias, SiLU, unpatchify ----
        #pragma unroll
        for (int h = 0; h < 2; h++) {
            const int grow = tile * TILE_M + warp * 16 + u + h * 8;
            const int bidx = grow >> 6;
            const int c64  = grow & 63;
            const int rrb  = (c64 >> 3) << 2;
            const int clb  = (c64 & 7) << 2;
            float* outb = out + ((size_t)bidx << 12);
            #pragma unroll
            for (int nt = 0; nt < 8; nt++) {
                const int o0 = nt * 8 + q * 2;
                float y0 = rs[h] * (acc[nt][h * 2 + 0] - mu[h] * sS[o0])     + sbp[o0];
                float y1 = rs[h] * (acc[nt][h * 2 + 1] - mu[h] * sS[o0 + 1]) + sbp[o0 + 1];
                float2 v;
                v.x = y0 / (1.f + __expf(-y0));
                v.y = y1 / (1.f + __expf(-y1));
                const int ch = o0 >> 4;
                const int rr = rrb + ((o0 >> 2) & 3);
                const int cl = clb + (o0 & 3);
                *(float2*)&outb[((ch * 32 + rr) << 5) + cl] = v;
            }
        }

        __syncthreads();
        if (tid == 0) s_next = atomicAdd(&d_ctr, 1u);
        __syncthreads();
        tile = s_next;
    }
}

extern "C" void kernel_launch(void* const* d_in, const int* in_sizes, int n_in,
                              void* d_out, int out_size)
{
    const float* x   = (const float*)d_in[0];
    const float* lnw = (const float*)d_in[1];
    const float* lnb = (const float*)d_in[2];
    const float* W   = (const float*)d_in[3];
    const float* b   = (const float*)d_in[4];
    float* out = (float*)d_out;

    cudaFuncSetAttribute(ln_gemm_silu,
                         cudaFuncAttributeMaxDynamicSharedMemorySize, SMEM_DYN_BYTES);

    int dev = 0, sms = 148;
    cudaGetDevice(&dev);
    cudaDeviceGetAttribute(&sms, cudaDevAttrMultiProcessorCount, dev);
    unsigned grid = (unsigned)(3 * sms);
    if (grid > NTILES) grid = NTILES;

    prep<<<(ODIM * KDIM + 255) / 256, 256>>>(W, lnw, lnb, b, grid);
    ln_gemm_silu<<<grid, 256, SMEM_DYN_BYTES>>>(x, out);
}

// round 15
// speedup vs baseline: 1.7533x; 1.7533x over previous
#include <cuda_runtime.h>
#include <cuda_fp16.h>
#include <cstdint>
#include <math.h>

// LayerNorm(768) -> Linear(768->64) -> SiLU -> unpatchify, fused.
// LN folded into epilogue: y = rstd*(x@W'^T - mu*S) + b', W' = W*ln_w (fp16).
// fp16 mma.sync.m16n8k16. Warp-autonomous: each warp owns 16 rows x all 64
// cols, streams x through a private 4-stage cp.async smem ring (depth 3).
// 2 CTAs/SM. cp.async line-coalesced: one instruction = 4 full 128B lines.
// W' 32k-interleaved: one LDG.128 per nt per slab (L1-resident, 96 KB).

#define KDIM 768
#define ODIM 64
#define TILE_M 128
#define NTILES 1024            // 131072 / 128
#define NSLABS 24              // k-slabs of 32 floats (128B)

#define STAGE_F 512            // floats per warp-stage (16 rows x 32)
#define WARP_F  (4 * STAGE_F)  // 4-stage ring per warp
#define SMEM_DYN_BYTES (8 * WARP_F * 4)   // 64 KB per CTA

__device__ __half d_Wh[24 * ODIM * 32];   // [slab][o][32k frag-interleaved]
__device__ float d_S[ODIM];
__device__ float d_bp[ODIM];
__device__ unsigned d_ctr;

static __device__ __forceinline__ uint32_t s2u(const void* p) {
    uint32_t a;
    asm("{ .reg .u64 t; cvta.to.shared.u64 t, %1; cvt.u32.u64 %0, t; }" : "=r"(a) : "l"(p));
    return a;
}
static __device__ __forceinline__ uint32_t pack2(float lo, float hi) {
    uint32_t r;
    asm("cvt.rn.f16x2.f32 %0, %1, %2;" : "=r"(r) : "f"(hi), "f"(lo));
    return r;
}
static __device__ __forceinline__ void mma_f16(float* d,
    uint32_t a0, uint32_t a1, uint32_t a2, uint32_t a3,
    uint32_t b0, uint32_t b1)
{
    asm volatile(
        "mma.sync.aligned.m16n8k16.row.col.f32.f16.f16.f32 "
        "{%0,%1,%2,%3}, {%4,%5,%6,%7}, {%8,%9}, {%0,%1,%2,%3};"
        : "+f"(d[0]), "+f"(d[1]), "+f"(d[2]), "+f"(d[3])
        : "r"(a0), "r"(a1), "r"(a2), "r"(a3), "r"(b0), "r"(b1));
}
static __device__ __forceinline__ void cp16(uint32_t dst, const void* src) {
    asm volatile("cp.async.cg.shared.global [%0], [%1], 16;"
                 :: "r"(dst), "l"(src) : "memory");
}

// ---------------- merged prep kernel ----------------
// 32k interleave: k = s*32 + kl32; kc = kl32>>4, kl = kl32&15
// pos32 = ((kl&7)>>1)*8 + kc*4 + ((kl>>3)&1)*2 + (kl&1)
// -> lane q reads uint4 #q: {kc0 b0, kc0 b1, kc1 b0, kc1 b1}
__global__ void prep(const float* __restrict__ W, const float* __restrict__ lnw,
                     const float* __restrict__ lnb, const float* __restrict__ b,
                     unsigned ctr_init)
{
    __shared__ float red[2][8];
    const int bid = blockIdx.x, t = threadIdx.x;
    const int idx = bid * 256 + t;
    if (idx == 0) d_ctr = ctr_init;

    if (idx < ODIM * KDIM) {
        int o = idx / KDIM, k = idx - o * KDIM;
        int kl32 = k & 31;
        int kc = kl32 >> 4, kl = kl32 & 15;
        int pos = ((kl & 7) >> 1) * 8 + kc * 4 + ((kl >> 3) & 1) * 2 + (kl & 1);
        d_Wh[((k >> 5) * ODIM + o) * 32 + pos] = __float2half_rn(W[idx] * lnw[k]);
    }

    if (bid < ODIM) {
        const int o = bid;
        float s = 0.f, bs = 0.f;
        for (int k = t; k < KDIM; k += 256) {
            float w = W[o * KDIM + k];
            s  += __half2float(__float2half_rn(w * lnw[k]));
            bs += lnb[k] * w;
        }
        #pragma unroll
        for (int d = 16; d; d >>= 1) {
            s  += __shfl_xor_sync(0xffffffffu, s, d);
            bs += __shfl_xor_sync(0xffffffffu, bs, d);
        }
        if ((t & 31) == 0) { red[0][t >> 5] = s; red[1][t >> 5] = bs; }
        __syncthreads();
        if (t == 0) {
            float S = 0.f, B = 0.f;
            #pragma unroll
            for (int i = 0; i < 8; i++) { S += red[0][i]; B += red[1][i]; }
            d_S[o] = S;
            d_bp[o] = b[o] + B;
        }
    }
}

// ---------------- main kernel ----------------
extern __shared__ float sx[];

__global__ void __launch_bounds__(256, 2)
ln_gemm_silu(const float* __restrict__ x, float* __restrict__ out)
{
    __shared__ float sS[64], sbp[64];
    __shared__ unsigned s_next;

    const int tid  = threadIdx.x;
    const int lane = tid & 31;
    const int warp = tid >> 5;

    // consumer mapping: warp owns rows warp*16 + {u, u+8}, all 64 cols
    const int u = lane >> 2;
    const int q = lane & 3;

    // producer mapping (line-coalesced): lane -> row r0 = lane>>3 (+4i),
    // chunk c = lane&7. One cp.async instr = rows 4i..4i+3 x 128B = 4 lines.
    const int pr0 = lane >> 3;     // 0..3
    const int pc  = lane & 7;      // 16B chunk within row

    if (tid < ODIM) { sS[tid] = d_S[tid]; sbp[tid] = d_bp[tid]; }
    __syncthreads();

    const uint32_t swb = s2u(sx) + warp * (WARP_F * 4);   // warp smem base (bytes)

    // per-lane swizzled byte offset within a stage (row pr0; +i*512 for row+4i)
    const uint32_t pswl = (uint32_t)(pr0 * 128 + ((pc ^ ((pr0 & 3) << 1)) << 4));

    // consumer float offsets within a stage (rows u, u+8 share (r&3) swizzle)
    const int swl = (u & 3) << 1;
    const int pos = (q & 1) << 1;
    int coff[2][2];   // [kc][c-half] word offsets (row u; add 256 for u+8)
    #pragma unroll
    for (int kc = 0; kc < 2; kc++) {
        int c0 = kc * 4 + (q >> 1);
        coff[kc][0] = (((c0       ^ swl) << 2) + pos);
        coff[kc][1] = ((((c0 + 2) ^ swl) << 2) + pos);
    }
    const int rowu  = u * 32;
    const int rowu8 = (u + 8) * 32;

    const uint4* __restrict__ Wv = (const uint4*)d_Wh;

    unsigned tile = blockIdx.x;
    while (tile < NTILES) {
        float acc[8][4];
        #pragma unroll
        for (int nt = 0; nt < 8; nt++)
            #pragma unroll
            for (int c = 0; c < 4; c++) acc[nt][c] = 0.f;

        float st0 = 0.f, st1 = 0.f, st2 = 0.f, st3 = 0.f;

        // gmem base for this lane: row (warp*16 + pr0), chunk pc
        const char* gx = (const char*)(x + (size_t)(tile * TILE_M + warp * 16 + pr0) * KDIM)
                       + pc * 16;

        // ---- prologue: issue slabs 0..2 ----
        #pragma unroll
        for (int s = 0; s < 3; s++) {
            uint32_t d = swb + s * 2048 + pswl;
            const char* g = gx + s * 128;
            #pragma unroll
            for (int i = 0; i < 4; i++)
                cp16(d + i * 512, g + (size_t)i * 4 * (KDIM * 4));
            asm volatile("cp.async.commit_group;" ::: "memory");
        }

        #pragma unroll 2
        for (int s = 0; s < NSLABS; s++) {
            // issue slab s+3 (stage reuse safe: prev iter's mma.sync consumed it)
            if (s + 3 < NSLABS) {
                uint32_t d = swb + ((s + 3) & 3) * 2048 + pswl;
                const char* g = gx + (s + 3) * 128;
                #pragma unroll
                for (int i = 0; i < 4; i++)
                    cp16(d + i * 512, g + (size_t)i * 4 * (KDIM * 4));
            }
            asm volatile("cp.async.commit_group;" ::: "memory");
            asm volatile("cp.async.wait_group 3;" ::: "memory");

            const float* sb = sx + warp * WARP_F + (s & 3) * STAGE_F;

            // load fragments from smem, stats, pack
            uint32_t af[2][4];
            #pragma unroll
            for (int kc = 0; kc < 2; kc++) {
                float2 vul = *(const float2*)&sb[rowu  + coff[kc][0]];
                float2 vuh = *(const float2*)&sb[rowu  + coff[kc][1]];
                float2 v8l = *(const float2*)&sb[rowu8 + coff[kc][0]];
                float2 v8h = *(const float2*)&sb[rowu8 + coff[kc][1]];
                st0 += vul.x + vul.y + vuh.x + vuh.y;
                st1 += vul.x*vul.x + vul.y*vul.y + vuh.x*vuh.x + vuh.y*vuh.y;
                st2 += v8l.x + v8l.y + v8h.x + v8h.y;
                st3 += v8l.x*v8l.x + v8l.y*v8l.y + v8h.x*v8h.x + v8h.y*v8h.y;
                af[kc][0] = pack2(vul.x, vul.y);   // (u,   2q)
                af[kc][1] = pack2(v8l.x, v8l.y);   // (u+8, 2q)
                af[kc][2] = pack2(vuh.x, vuh.y);   // (u,   2q+8)
                af[kc][3] = pack2(v8h.x, v8h.y);   // (u+8, 2q+8)
            }

            // W fragments: one LDG.128 per nt (both kc), then 2 MMAs
            const uint4* wb = Wv + (size_t)(s * ODIM + u) * 4 + q;
            #pragma unroll
            for (int nt = 0; nt < 8; nt++) {
                uint4 bv = __ldg(wb + nt * 32);   // +8 o-rows per nt
                mma_f16(acc[nt], af[0][0], af[0][1], af[0][2], af[0][3], bv.x, bv.y);
                mma_f16(acc[nt], af[1][0], af[1][1], af[1][2], af[1][3], bv.z, bv.w);
            }
        }

        // ---- row stats: reduce over 4 q-lanes sharing each row ----
        st0 += __shfl_xor_sync(0xffffffffu, st0, 1);
        st1 += __shfl_xor_sync(0xffffffffu, st1, 1);
        st2 += __shfl_xor_sync(0xffffffffu, st2, 1);
        st3 += __shfl_xor_sync(0xffffffffu, st3, 1);
        st0 += __shfl_xor_sync(0xffffffffu, st0, 2);
        st1 += __shfl_xor_sync(0xffffffffu, st1, 2);
        st2 += __shfl_xor_sync(0xffffffffu, st2, 2);
        st3 += __shfl_xor_sync(0xffffffffu, st3, 2);

        float mu[2], rs[2];
        mu[0] = st0 * (1.f / 768.f);
        mu[1] = st2 * (1.f / 768.f);
        rs[0] = rsqrtf(st1 * (1.f / 768.f) - mu[0] * mu[0] + 1e-5f);
        rs[1] = rsqrtf(st3 * (1.f / 768.f) - mu[1] * mu[1] + 1e-5f);

        // ---- epilogue: LN-correct, bias, SiLU, unpatchify ----
        #pragma unroll
        for (int h = 0; h < 2; h++) {
            const int grow = tile * TILE_M + warp * 16 + u + h * 8;
            const int bidx = grow >> 6;
            const int c64  = grow & 63;
            const int rrb  = (c64 >> 3) << 2;
            const int clb  = (c64 & 7) << 2;
            float* outb = out + ((size_t)bidx << 12);
            #pragma unroll
            for (int nt = 0; nt < 8; nt++) {
                const int o0 = nt * 8 + q * 2;
                float y0 = rs[h] * (acc[nt][h * 2 + 0] - mu[h] * sS[o0])     + sbp[o0];
                float y1 = rs[h] * (acc[nt][h * 2 + 1] - mu[h] * sS[o0 + 1]) + sbp[o0 + 1];
                float2 v;
                v.x = y0 / (1.f + __expf(-y0));
                v.y = y1 / (1.f + __expf(-y1));
                const int ch = o0 >> 4;
                const int rr = rrb + ((o0 >> 2) & 3);
                const int cl = clb + (o0 & 3);
                *(float2*)&outb[((ch * 32 + rr) << 5) + cl] = v;
            }
        }

        __syncthreads();
        if (tid == 0) s_next = atomicAdd(&d_ctr, 1u);
        __syncthreads();
        tile = s_next;
    }
}

extern "C" void kernel_launch(void* const* d_in, const int* in_sizes, int n_in,
                              void* d_out, int out_size)
{
    const float* x   = (const float*)d_in[0];
    const float* lnw = (const float*)d_in[1];
    const float* lnb = (const float*)d_in[2];
    const float* W   = (const float*)d_in[3];
    const float* b   = (const float*)d_in[4];
    float* out = (float*)d_out;

    cudaFuncSetAttribute(ln_gemm_silu,
                         cudaFuncAttributeMaxDynamicSharedMemorySize, SMEM_DYN_BYTES);

    int dev = 0, sms = 148;
    cudaGetDevice(&dev);
    cudaDeviceGetAttribute(&sms, cudaDevAttrMultiProcessorCount, dev);
    unsigned grid = (unsigned)(2 * sms);
    if (grid > NTILES) grid = NTILES;

    prep<<<(ODIM * KDIM + 255) / 256, 256>>>(W, lnw, lnb, b, grid);
    ln_gemm_silu<<<grid, 256, SMEM_DYN_BYTES>>>(x, out);
}

// round 16
// speedup vs baseline: 2.0206x; 1.1525x over previous
#include <cuda_runtime.h>
#include <cuda_fp16.h>
#include <cstdint>
#include <math.h>

// LayerNorm(768) -> Linear(768->64) -> SiLU -> unpatchify, fused.
// LN folded into epilogue: y = rstd*(x@W'^T - mu*S) + b', W' = W*ln_w (fp16).
// fp16 mma.sync.m16n8k16. Warp-autonomous, per-warp work stealing over
// 16-row units. x streamed via per-warp 2-stage cp.async ring with 256B
// row-granules (DRAM row-buffer friendly), half-stage commit groups.
// W' lives in smem (96KB); 1 CTA x 512 threads per SM.

#define KDIM 768
#define ODIM 64
#define NUNITS 8192            // 131072 rows / 16
#define NSTAGES 12             // K stages of 64 floats (256B per row)

#define W_SMEM_B  98304        // 24*64*32 halves
#define WP_RING_B 8192         // 2 stages x 4KB
#define SMEM_DYN  (W_SMEM_B + 16 * WP_RING_B)   // 229376 B

__device__ __align__(16) __half d_Wh[24 * ODIM * 32];   // [slab][o][frag pos]
__device__ float d_S[ODIM];
__device__ float d_bp[ODIM];
__device__ unsigned d_ctr;

static __device__ __forceinline__ uint32_t s2u(const void* p) {
    uint32_t a;
    asm("{ .reg .u64 t; cvta.to.shared.u64 t, %1; cvt.u32.u64 %0, t; }" : "=r"(a) : "l"(p));
    return a;
}
static __device__ __forceinline__ uint32_t pack2(float lo, float hi) {
    uint32_t r;
    asm("cvt.rn.f16x2.f32 %0, %1, %2;" : "=r"(r) : "f"(hi), "f"(lo));
    return r;
}
static __device__ __forceinline__ void mma_f16(float* d,
    uint32_t a0, uint32_t a1, uint32_t a2, uint32_t a3,
    uint32_t b0, uint32_t b1)
{
    asm volatile(
        "mma.sync.aligned.m16n8k16.row.col.f32.f16.f16.f32 "
        "{%0,%1,%2,%3}, {%4,%5,%6,%7}, {%8,%9}, {%0,%1,%2,%3};"
        : "+f"(d[0]), "+f"(d[1]), "+f"(d[2]), "+f"(d[3])
        : "r"(a0), "r"(a1), "r"(a2), "r"(a3), "r"(b0), "r"(b1));
}
static __device__ __forceinline__ void cp16(uint32_t dst, const void* src) {
    asm volatile("cp.async.cg.shared.global [%0], [%1], 16;"
                 :: "r"(dst), "l"(src) : "memory");
}
static __device__ __forceinline__ void cp_commit() {
    asm volatile("cp.async.commit_group;" ::: "memory");
}
static __device__ __forceinline__ void cp_wait2() {
    asm volatile("cp.async.wait_group 2;" ::: "memory");
}

// ---------------- merged prep kernel ----------------
// 32k frag interleave: k = sl*32 + kl32; kc = kl32>>4, kl = kl32&15
// pos = ((kl&7)>>1)*8 + kc*4 + ((kl>>3)&1)*2 + (kl&1)
__global__ void prep(const float* __restrict__ W, const float* __restrict__ lnw,
                     const float* __restrict__ lnb, const float* __restrict__ b,
                     unsigned ctr_init)
{
    __shared__ float red[2][8];
    const int bid = blockIdx.x, t = threadIdx.x;
    const int idx = bid * 256 + t;
    if (idx == 0) d_ctr = ctr_init;

    if (idx < ODIM * KDIM) {
        int o = idx / KDIM, k = idx - o * KDIM;
        int kl32 = k & 31;
        int kc = kl32 >> 4, kl = kl32 & 15;
        int pos = ((kl & 7) >> 1) * 8 + kc * 4 + ((kl >> 3) & 1) * 2 + (kl & 1);
        d_Wh[((k >> 5) * ODIM + o) * 32 + pos] = __float2half_rn(W[idx] * lnw[k]);
    }

    if (bid < ODIM) {
        const int o = bid;
        float s = 0.f, bs = 0.f;
        for (int k = t; k < KDIM; k += 256) {
            float w = W[o * KDIM + k];
            s  += __half2float(__float2half_rn(w * lnw[k]));
            bs += lnb[k] * w;
        }
        #pragma unroll
        for (int d = 16; d; d >>= 1) {
            s  += __shfl_xor_sync(0xffffffffu, s, d);
            bs += __shfl_xor_sync(0xffffffffu, bs, d);
        }
        if ((t & 31) == 0) { red[0][t >> 5] = s; red[1][t >> 5] = bs; }
        __syncthreads();
        if (t == 0) {
            float S = 0.f, B = 0.f;
            #pragma unroll
            for (int i = 0; i < 8; i++) { S += red[0][i]; B += red[1][i]; }
            d_S[o] = S;
            d_bp[o] = b[o] + B;
        }
    }
}

// ---------------- main kernel ----------------
extern __shared__ char smc[];

__global__ void __launch_bounds__(512, 1)
ln_gemm_silu(const float* __restrict__ x, float* __restrict__ out)
{
    __shared__ float sS[64], sbp[64];

    const int tid  = threadIdx.x;
    const int lane = tid & 31;
    const int warp = tid >> 5;

    // ---- one-time: copy W' into smem; load S/bp ----
    {
        const uint4* wsrc = (const uint4*)d_Wh;
        uint4* wdst = (uint4*)smc;
        for (int i = tid; i < W_SMEM_B / 16; i += 512) wdst[i] = wsrc[i];
        if (tid < ODIM) { sS[tid] = d_S[tid]; sbp[tid] = d_bp[tid]; }
    }
    __syncthreads();

    // consumer mapping: rows {u, u+8} of the unit, all 64 cols
    const int u = lane >> 2;
    const int q = lane & 3;
    // producer mapping: r0 = lane>>3 (rows r0+4i), cc = lane&7 (16B chunk)
    const int r0 = lane >> 3;
    const int cc = lane & 7;

    float* ring = (float*)(smc + W_SMEM_B + warp * WP_RING_B);
    const uint32_t ring_u = s2u(ring);
    const uint32_t pswl = (uint32_t)(r0 * 256 + ((cc ^ (r0 << 1)) << 4));

    // consumer swizzled float offsets (within a 32-float slab of a stage-row)
    const int swl = (u & 3) << 1;
    const int pos = (q & 1) << 1;
    int coff[2][2];
    #pragma unroll
    for (int kc = 0; kc < 2; kc++) {
        int c0 = kc * 4 + (q >> 1);
        coff[kc][0] = (((c0    ) ^ swl) << 2) + pos;
        coff[kc][1] = (((c0 + 2) ^ swl) << 2) + pos;
    }
    const int rowu  = u * 64;
    const int rowu8 = (u + 8) * 64;

    unsigned unit = blockIdx.x * 16 + warp;
    while (unit < NUNITS) {
        float acc[8][4];
        #pragma unroll
        for (int nt = 0; nt < 8; nt++)
            #pragma unroll
            for (int c = 0; c < 4; c++) acc[nt][c] = 0.f;

        float st0 = 0.f, st1 = 0.f, st2 = 0.f, st3 = 0.f;

        const char* gx = (const char*)x + (size_t)(unit * 16 + r0) * (KDIM * 4) + cc * 16;

        // ---- prologue: stage 0, groups A then B ----
        #pragma unroll
        for (int g = 0; g < 2; g++) {
            uint32_t d = ring_u + pswl + g * 128;
            const char* gsrc = gx + g * 128;
            #pragma unroll
            for (int i = 0; i < 4; i++) cp16(d + i * 1024, gsrc + (size_t)i * 12288);
            cp_commit();
        }

        #pragma unroll 2
        for (int s = 0; s < NSTAGES; s++) {
            const float* sb = ring + (s & 1) * 1024;
            const char* wbs = smc + (size_t)(s * 2) * 64 * 64;  // slab s*2 W base (64B/o-row)

            #pragma unroll
            for (int h = 0; h < 2; h++) {
                // issue next stage's group h; commit unconditionally (empty ok)
                if (s + 1 < NSTAGES) {
                    uint32_t d = ring_u + ((s + 1) & 1) * 4096 + pswl + h * 128;
                    const char* gsrc = gx + (s + 1) * 256 + h * 128;
                    #pragma unroll
                    for (int i = 0; i < 4; i++) cp16(d + i * 1024, gsrc + (size_t)i * 12288);
                }
                cp_commit();
                cp_wait2();   // oldest pending group (this stage's group h) landed

                // consume slab h of stage s
                uint32_t af[2][4];
                #pragma unroll
                for (int kc = 0; kc < 2; kc++) {
                    float2 vul = *(const float2*)&sb[rowu  + h * 32 + coff[kc][0]];
                    float2 vuh = *(const float2*)&sb[rowu  + h * 32 + coff[kc][1]];
                    float2 v8l = *(const float2*)&sb[rowu8 + h * 32 + coff[kc][0]];
                    float2 v8h = *(const float2*)&sb[rowu8 + h * 32 + coff[kc][1]];
                    st0 += vul.x + vul.y + vuh.x + vuh.y;
                    st1 += vul.x*vul.x + vul.y*vul.y + vuh.x*vuh.x + vuh.y*vuh.y;
                    st2 += v8l.x + v8l.y + v8h.x + v8h.y;
                    st3 += v8l.x*v8l.x + v8l.y*v8l.y + v8h.x*v8h.x + v8h.y*v8h.y;
                    af[kc][0] = pack2(vul.x, vul.y);   // (u,   2q)
                    af[kc][1] = pack2(v8l.x, v8l.y);   // (u+8, 2q)
                    af[kc][2] = pack2(vuh.x, vuh.y);   // (u,   2q+8)
                    af[kc][3] = pack2(v8h.x, v8h.y);   // (u+8, 2q+8)
                }

                // W fragments from smem: one LDS.128 per nt
                const char* wb = wbs + (size_t)h * 4096 + ((u * 4 + q) << 4);
                #pragma unroll
                for (int nt = 0; nt < 8; nt++) {
                    uint4 bv = *(const uint4*)(wb + nt * 512);
                    mma_f16(acc[nt], af[0][0], af[0][1], af[0][2], af[0][3], bv.x, bv.y);
                    mma_f16(acc[nt], af[1][0], af[1][1], af[1][2], af[1][3], bv.z, bv.w);
                }
            }
        }

        // ---- row stats: reduce over 4 q-lanes sharing each row ----
        st0 += __shfl_xor_sync(0xffffffffu, st0, 1);
        st1 += __shfl_xor_sync(0xffffffffu, st1, 1);
        st2 += __shfl_xor_sync(0xffffffffu, st2, 1);
        st3 += __shfl_xor_sync(0xffffffffu, st3, 1);
        st0 += __shfl_xor_sync(0xffffffffu, st0, 2);
        st1 += __shfl_xor_sync(0xffffffffu, st1, 2);
        st2 += __shfl_xor_sync(0xffffffffu, st2, 2);
        st3 += __shfl_xor_sync(0xffffffffu, st3, 2);

        float mu[2], rs[2];
        mu[0] = st0 * (1.f / 768.f);
        mu[1] = st2 * (1.f / 768.f);
        rs[0] = rsqrtf(st1 * (1.f / 768.f) - mu[0] * mu[0] + 1e-5f);
        rs[1] = rsqrtf(st3 * (1.f / 768.f) - mu[1] * mu[1] + 1e-5f);

        // ---- epilogue: LN-correct, bias, SiLU, unpatchify ----
        #pragma unroll
        for (int h = 0; h < 2; h++) {
            const int grow = unit * 16 + u + h * 8;
            const int bidx = grow >> 6;
            const int c64  = grow & 63;
            const int rrb  = (c64 >> 3) << 2;
            const int clb  = (c64 & 7) << 2;
            float* outb = out + ((size_t)bidx << 12);
            #pragma unroll
            for (int nt = 0; nt < 8; nt++) {
                const int o0 = nt * 8 + q * 2;
                float y0 = rs[h] * (acc[nt][h * 2 + 0] - mu[h] * sS[o0])     + sbp[o0];
                float y1 = rs[h] * (acc[nt][h * 2 + 1] - mu[h] * sS[o0 + 1]) + sbp[o0 + 1];
                float2 v;
                v.x = y0 / (1.f + __expf(-y0));
                v.y = y1 / (1.f + __expf(-y1));
                const int ch = o0 >> 4;
                const int rr = rrb + ((o0 >> 2) & 3);
                const int cl = clb + (o0 & 3);
                *(float2*)&outb[((ch * 32 + rr) << 5) + cl] = v;
            }
        }

        // ---- per-warp work steal ----
        unsigned nx = 0;
        if (lane == 0) nx = atomicAdd(&d_ctr, 1u);
        unit = __shfl_sync(0xffffffffu, nx, 0);
    }
}

extern "C" void kernel_launch(void* const* d_in, const int* in_sizes, int n_in,
                              void* d_out, int out_size)
{
    const float* x   = (const float*)d_in[0];
    const float* lnw = (const float*)d_in[1];
    const float* lnb = (const float*)d_in[2];
    const float* W   = (const float*)d_in[3];
    const float* b   = (const float*)d_in[4];
    float* out = (float*)d_out;

    cudaFuncSetAttribute(ln_gemm_silu,
                         cudaFuncAttributeMaxDynamicSharedMemorySize, SMEM_DYN);

    int dev = 0, sms = 148;
    cudaGetDevice(&dev);
    cudaDeviceGetAttribute(&sms, cudaDevAttrMultiProcessorCount, dev);
    unsigned grid = (unsigned)sms;

    prep<<<(ODIM * KDIM + 255) / 256, 256>>>(W, lnw, lnb, b, grid * 16u);
    ln_gemm_silu<<<grid, 512, SMEM_DYN>>>(x, out);
}